// round 1
// baseline (speedup 1.0000x reference)
#include <cuda_runtime.h>
#include <math.h>

#define NTOK 16384
#define DDIM 2048
#define NE   64
#define TM   64
#define KT   64
#define NTHREADS 128
#define NGRP 8
#define TOPK 8
#define TOPG 4

__device__ __forceinline__ unsigned long long pack2(float a, float b) {
    unsigned long long r;
    asm("mov.b64 %0, {%1,%2};" : "=l"(r) : "f"(a), "f"(b));
    return r;
}
__device__ __forceinline__ void unpack2(unsigned long long v, float& a, float& b) {
    asm("mov.b64 {%0,%1}, %2;" : "=f"(a), "=f"(b) : "l"(v));
}
__device__ __forceinline__ unsigned long long ffma2(unsigned long long a,
                                                    unsigned long long b,
                                                    unsigned long long c) {
    unsigned long long d;
    asm("fma.rn.f32x2 %0, %1, %2, %3;" : "=l"(d) : "l"(a), "l"(b), "l"(c));
    return d;
}

__global__ void __launch_bounds__(NTHREADS) gate_kernel(
    const float* __restrict__ x,     // [NTOK, DDIM]
    const float* __restrict__ W,     // [NE, DDIM]
    const float* __restrict__ bvec,  // [NE]
    const float* __restrict__ bias,  // [1, NE]
    float* __restrict__ out)         // [NTOK*8 weights | NTOK*8 idx-as-float]
{
    // xs/ws: [KT][64] transposed tiles with k-quad XOR swizzle on the row-quad.
    __shared__ float smem[2 * KT * 64];
    float* xs = smem;
    float* ws = smem + KT * 64;

    const int tid = threadIdx.x;
    const int tx = tid & 15;   // expert group: experts 4*tx .. 4*tx+3
    const int ty = tid >> 4;   // token group : tokens  8*ty .. 8*ty+7
    const int t0 = blockIdx.x * TM;

    const int lc = tid & 15;   // k-quad index for cooperative loads
    const int lr = tid >> 4;   // row base (0..7)

    // acc[i][j]: f32x2 over tokens (8*ty+2i, 8*ty+2i+1), expert 4*tx+j
    unsigned long long acc[4][4];
#pragma unroll
    for (int i = 0; i < 4; i++)
#pragma unroll
        for (int j = 0; j < 4; j++) acc[i][j] = 0ull;

    for (int k0 = 0; k0 < DDIM; k0 += KT) {
        __syncthreads();
        // ---- load x tile [TM tokens][KT k] -> xs[k][token] (swizzled) ----
#pragma unroll
        for (int it = 0; it < 8; it++) {
            int row = lr + it * 8;  // token within tile
            float4 v = *reinterpret_cast<const float4*>(
                x + (size_t)(t0 + row) * DDIM + k0 + 4 * lc);
            int qp = (((row >> 2) ^ lc) << 2) + (row & 3);
            xs[(4 * lc + 0) * 64 + qp] = v.x;
            xs[(4 * lc + 1) * 64 + qp] = v.y;
            xs[(4 * lc + 2) * 64 + qp] = v.z;
            xs[(4 * lc + 3) * 64 + qp] = v.w;
        }
        // ---- load W tile [NE experts][KT k] -> ws[k][expert] (swizzled) ----
#pragma unroll
        for (int it = 0; it < 8; it++) {
            int row = lr + it * 8;  // expert
            float4 v = *reinterpret_cast<const float4*>(
                W + (size_t)row * DDIM + k0 + 4 * lc);
            int qp = (((row >> 2) ^ lc) << 2) + (row & 3);
            ws[(4 * lc + 0) * 64 + qp] = v.x;
            ws[(4 * lc + 1) * 64 + qp] = v.y;
            ws[(4 * lc + 2) * 64 + qp] = v.z;
            ws[(4 * lc + 3) * 64 + qp] = v.w;
        }
        __syncthreads();

        // ---- compute ----
#pragma unroll 4
        for (int kq = 0; kq < KT / 4; kq++) {
            const int swz = kq & 15;
            const int qa = (((2 * ty)     ^ swz) << 2);
            const int qb = (((2 * ty + 1) ^ swz) << 2);
            const int qw = ((tx ^ swz) << 2);
#pragma unroll
            for (int j4 = 0; j4 < 4; j4++) {
                const int k = kq * 4 + j4;
                ulonglong2 xA = *reinterpret_cast<const ulonglong2*>(xs + k * 64 + qa);
                ulonglong2 xB = *reinterpret_cast<const ulonglong2*>(xs + k * 64 + qb);
                float4 wv = *reinterpret_cast<const float4*>(ws + k * 64 + qw);
                unsigned long long xp0 = xA.x, xp1 = xA.y, xp2 = xB.x, xp3 = xB.y;
                unsigned long long wp0 = pack2(wv.x, wv.x);
                unsigned long long wp1 = pack2(wv.y, wv.y);
                unsigned long long wp2 = pack2(wv.z, wv.z);
                unsigned long long wp3 = pack2(wv.w, wv.w);
                acc[0][0] = ffma2(xp0, wp0, acc[0][0]);
                acc[0][1] = ffma2(xp0, wp1, acc[0][1]);
                acc[0][2] = ffma2(xp0, wp2, acc[0][2]);
                acc[0][3] = ffma2(xp0, wp3, acc[0][3]);
                acc[1][0] = ffma2(xp1, wp0, acc[1][0]);
                acc[1][1] = ffma2(xp1, wp1, acc[1][1]);
                acc[1][2] = ffma2(xp1, wp2, acc[1][2]);
                acc[1][3] = ffma2(xp1, wp3, acc[1][3]);
                acc[2][0] = ffma2(xp2, wp0, acc[2][0]);
                acc[2][1] = ffma2(xp2, wp1, acc[2][1]);
                acc[2][2] = ffma2(xp2, wp2, acc[2][2]);
                acc[2][3] = ffma2(xp2, wp3, acc[2][3]);
                acc[3][0] = ffma2(xp3, wp0, acc[3][0]);
                acc[3][1] = ffma2(xp3, wp1, acc[3][1]);
                acc[3][2] = ffma2(xp3, wp2, acc[3][2]);
                acc[3][3] = ffma2(xp3, wp3, acc[3][3]);
            }
        }
    }

    // ---- epilogue: sigmoid -> smem score matrix sc[token][expert] ----
    __syncthreads();
    float* sc = smem;  // [TM][65], 4160 floats, fits in the 8192-float buffer
#pragma unroll
    for (int i = 0; i < 4; i++) {
#pragma unroll
        for (int j = 0; j < 4; j++) {
            float lo, hi;
            unpack2(acc[i][j], lo, hi);
            const int e = 4 * tx + j;
            const float bb = bvec[e];
            const int tA = 8 * ty + 2 * i;
            sc[(tA + 0) * 65 + e] = 1.0f / (1.0f + expf(-(lo + bb)));
            sc[(tA + 1) * 65 + e] = 1.0f / (1.0f + expf(-(hi + bb)));
        }
    }
    __syncthreads();

    // ---- routing: one thread per token, exact reference semantics ----
    if (tid < TM) {
        const int t = tid;
        const int gt = t0 + t;
        const float* row = sc + t * 65;

        float s[NE];
#pragma unroll
        for (int e = 0; e < NE; e++) s[e] = row[e] + bias[e];

        // group score = sum of top-2 within each group of 8
        float gs[NGRP];
#pragma unroll
        for (int g = 0; g < NGRP; g++) {
            float m1 = -1e30f, m2 = -1e30f;
#pragma unroll
            for (int j = 0; j < 8; j++) {
                float v = s[8 * g + j];
                if (v > m1) { m2 = m1; m1 = v; }
                else if (v > m2) { m2 = v; }
            }
            gs[g] = m1 + m2;
        }

        // top-4 groups (strict > keeps lowest index on ties, matching lax.top_k)
        int gmask = 0;
        for (int r = 0; r < TOPG; r++) {
            float bv = -1e30f; int bg = 0;
#pragma unroll
            for (int g = 0; g < NGRP; g++) {
                bool avail = !((gmask >> g) & 1);
                if (avail && gs[g] > bv) { bv = gs[g]; bg = g; }
            }
            gmask |= (1 << bg);
        }

        // top-8 experts among selected groups
        unsigned long long used = 0ull;
        for (int r = 0; r < TOPK; r++) {
            float bv = -1e30f; int be = 0;
#pragma unroll
            for (int e = 0; e < NE; e++) {
                bool ok = ((gmask >> (e >> 3)) & 1) && !((used >> e) & 1ull);
                if (ok && s[e] > bv) { bv = s[e]; be = e; }
            }
            used |= (1ull << be);
            out[(size_t)gt * TOPK + r] = row[be];                       // weight (no bias)
            out[(size_t)NTOK * TOPK + (size_t)gt * TOPK + r] = (float)be;  // index
        }
    }
}

extern "C" void kernel_launch(void* const* d_in, const int* in_sizes, int n_in,
                              void* d_out, int out_size) {
    const float* x    = (const float*)d_in[0];
    const float* W    = (const float*)d_in[1];
    const float* b    = (const float*)d_in[2];
    const float* bias = (const float*)d_in[3];
    float* out = (float*)d_out;
    gate_kernel<<<NTOK / TM, NTHREADS>>>(x, W, b, bias, out);
}